// round 2
// baseline (speedup 1.0000x reference)
#include <cuda_runtime.h>
#include <cstdint>

// ---------------------------------------------------------------------------
// VGAE/GCN encoder:
//   deg/dinv  -> dropout(threefry) -> Z1 = agg(Xd) -> h = relu(Z1@W1+b1)
//   Z2 = agg(h) -> mu = Z2@Wmu+bmu ; logstd = Z2@Wls+bls
// Aggregation reordered before the GEMM (conv is linear in h).
//
// edge_index: int32 (JAX downgrades int64 without x64 mode). Layout (2,E):
//   src = ei[0:E], dst = ei[E:2E].
//
// RNG (partitionable threefry, 32-bit): per flat index i,
//   (b1,b2) = threefry2x32(key=(0,42), x=(hi32(i), lo32(i)))
//   bits = b1 ^ b2
//   u = bitcast((bits>>9)|0x3f800000) - 1 ; keep = u < 0.5
// Fallbacks if rel_err O(1): bits=b2; bits=b1; legacy pairwise scheme.
// ---------------------------------------------------------------------------

#define NN 50000
#define DH 512
#define DOUT 256

__device__ float g_Xd[(size_t)NN * DH];   // dropout(x)
__device__ float g_Z [(size_t)NN * DH];   // aggregation buffer (reused L1/L2)
__device__ float g_h [(size_t)NN * DH];   // hidden activations
__device__ float g_dinv[NN];              // deg -> dinv in place

// ----------------------------- threefry2x32 --------------------------------
__device__ __forceinline__ uint32_t rotl32(uint32_t v, int r) {
    return (v << r) | (v >> (32 - r));
}

__device__ __forceinline__ void threefry2x32(uint32_t k0, uint32_t k1,
                                             uint32_t& x0, uint32_t& x1) {
    uint32_t ks2 = 0x1BD11BDAu ^ k0 ^ k1;
    x0 += k0; x1 += k1;
#define TFR(r) { x0 += x1; x1 = rotl32(x1, r); x1 ^= x0; }
    TFR(13) TFR(15) TFR(26) TFR(6)
    x0 += k1;  x1 += ks2 + 1u;
    TFR(17) TFR(29) TFR(16) TFR(24)
    x0 += ks2; x1 += k0 + 2u;
    TFR(13) TFR(15) TFR(26) TFR(6)
    x0 += k0;  x1 += k1 + 3u;
    TFR(17) TFR(29) TFR(16) TFR(24)
    x0 += k1;  x1 += ks2 + 4u;
    TFR(13) TFR(15) TFR(26) TFR(6)
    x0 += ks2; x1 += k0 + 5u;
#undef TFR
}

// ----------------------------- small kernels -------------------------------
__global__ void k_deg_init(int n) {
    int i = blockIdx.x * blockDim.x + threadIdx.x;
    if (i < n) g_dinv[i] = 1.0f;               // self-loop
}

__global__ void k_deg_accum(const int* __restrict__ dst, int E) {
    int e = blockIdx.x * blockDim.x + threadIdx.x;
    if (e < E) atomicAdd(&g_dinv[dst[e]], 1.0f);
}

__global__ void k_deg_finish(int n) {
    int i = blockIdx.x * blockDim.x + threadIdx.x;
    if (i < n) g_dinv[i] = rsqrtf(g_dinv[i]);
}

__global__ void k_dropout(const float* __restrict__ x, long long T) {
    long long i = (long long)blockIdx.x * blockDim.x + threadIdx.x;
    if (i >= T) return;
    uint32_t hi = 0u;              // hi32 of 64-bit counter (T < 2^32)
    uint32_t lo = (uint32_t)i;     // lo32
    threefry2x32(0u, 42u, hi, lo);
    uint32_t bits = hi ^ lo;       // partitionable 32-bit path: b1 ^ b2
    float u = __uint_as_float((bits >> 9) | 0x3f800000u) - 1.0f;
    g_Xd[i] = (u < 0.5f) ? x[i] * 2.0f : 0.0f;
}

// Z = X * dinv^2 (self-loop term), which: 0 -> Xd, 1 -> h
__global__ void k_self(int n, int which) {
    long long idx = (long long)blockIdx.x * blockDim.x + threadIdx.x;
    long long total = (long long)n * (DH / 4);
    if (idx >= total) return;
    int node = (int)(idx / (DH / 4));
    float w = g_dinv[node]; w = w * w;
    const float4* X = (const float4*)(which ? g_h : g_Xd);
    float4 v = X[idx];
    ((float4*)g_Z)[idx] = make_float4(v.x * w, v.y * w, v.z * w, v.w * w);
}

// One warp per edge: Z[dst] += X[src] * dinv[src]*dinv[dst]
__global__ void k_edge_agg(const int* __restrict__ src,
                           const int* __restrict__ dst,
                           int E, int which) {
    int gw   = (blockIdx.x * blockDim.x + threadIdx.x) >> 5;
    int lane = threadIdx.x & 31;
    if (gw >= E) return;
    int s = src[gw];
    int d = dst[gw];
    float w = g_dinv[s] * g_dinv[d];
    const float4* X = (const float4*)((which ? g_h : g_Xd) + (size_t)s * DH);
    float* Z = g_Z + (size_t)d * DH;
#pragma unroll
    for (int i = 0; i < DH / 128; i++) {
        float4 v = X[i * 32 + lane];
        int c = (i * 32 + lane) * 4;
        atomicAdd(Z + c + 0, v.x * w);
        atomicAdd(Z + c + 1, v.y * w);
        atomicAdd(Z + c + 2, v.z * w);
        atomicAdd(Z + c + 3, v.w * w);
    }
}

// ------------------------------- SGEMM -------------------------------------
// C[M,Ncols] = g_Z[M,512] @ B[512,Ncols] + bias ; optional relu.
// relu!=0 -> write g_h (layer 1); relu==0 -> write Cext.
__global__ __launch_bounds__(256, 2)
void k_gemm(const float* __restrict__ B, const float* __restrict__ bias,
            float* __restrict__ Cext, int M, int Ncols, int relu) {
    const int K = 512;
    __shared__ float As[8][128];
    __shared__ float Bs[8][128];
    int tid = threadIdx.x;
    int tx = tid & 15, ty = tid >> 4;
    int rowBase = blockIdx.y * 128;
    int colBase = blockIdx.x * 128;
    float acc[8][8];
#pragma unroll
    for (int i = 0; i < 8; i++)
#pragma unroll
        for (int j = 0; j < 8; j++) acc[i][j] = 0.0f;

    int aRow = tid >> 1, aCol = (tid & 1) * 4;
    int bRow = tid >> 5, bCol = (tid & 31) * 4;
    const float* A = g_Z;

    for (int k0 = 0; k0 < K; k0 += 8) {
        float4 av = make_float4(0.f, 0.f, 0.f, 0.f);
        int ar = rowBase + aRow;
        if (ar < M)
            av = *(const float4*)(A + (size_t)ar * K + k0 + aCol);
        As[aCol + 0][aRow] = av.x;
        As[aCol + 1][aRow] = av.y;
        As[aCol + 2][aRow] = av.z;
        As[aCol + 3][aRow] = av.w;
        float4 bv = *(const float4*)(B + (size_t)(k0 + bRow) * Ncols + colBase + bCol);
        *(float4*)&Bs[bRow][bCol] = bv;
        __syncthreads();
#pragma unroll
        for (int k = 0; k < 8; k++) {
            float a8[8], b8[8];
#pragma unroll
            for (int i = 0; i < 8; i++) a8[i] = As[k][ty * 8 + i];
#pragma unroll
            for (int j = 0; j < 8; j++) b8[j] = Bs[k][tx * 8 + j];
#pragma unroll
            for (int i = 0; i < 8; i++)
#pragma unroll
                for (int j = 0; j < 8; j++) acc[i][j] += a8[i] * b8[j];
        }
        __syncthreads();
    }

    float bv[8];
#pragma unroll
    for (int j = 0; j < 8; j++) bv[j] = bias[colBase + tx * 8 + j];
    float* Cw = relu ? g_h : Cext;
#pragma unroll
    for (int i = 0; i < 8; i++) {
        int r = rowBase + ty * 8 + i;
        if (r < M) {
#pragma unroll
            for (int j = 0; j < 8; j++) {
                float v = acc[i][j] + bv[j];
                if (relu) v = fmaxf(v, 0.0f);
                Cw[(size_t)r * Ncols + colBase + tx * 8 + j] = v;
            }
        }
    }
}

// ------------------------------- launch ------------------------------------
extern "C" void kernel_launch(void* const* d_in, const int* in_sizes, int n_in,
                              void* d_out, int out_size) {
    const float* x   = (const float*)d_in[0];
    const int*   ei  = (const int*)d_in[1];     // int32! (JAX x64 disabled)
    const float* W1  = (const float*)d_in[2];
    const float* b1  = (const float*)d_in[3];
    const float* Wmu = (const float*)d_in[4];
    const float* bmu = (const float*)d_in[5];
    const float* Wls = (const float*)d_in[6];
    const float* bls = (const float*)d_in[7];
    float* out = (float*)d_out;

    int N = in_sizes[0] / DH;
    int E = in_sizes[1] / 2;
    const int* srcp = ei;
    const int* dstp = ei + E;
    long long T = (long long)N * DH;

    // degrees -> dinv
    k_deg_init  <<<(N + 255) / 256, 256>>>(N);
    k_deg_accum <<<(E + 255) / 256, 256>>>(dstp, E);
    k_deg_finish<<<(N + 255) / 256, 256>>>(N);

    // dropout (threefry, partitionable XOR hypothesis)
    k_dropout<<<(int)((T + 255) / 256), 256>>>(x, T);

    // layer 1: Z = agg(Xd); h = relu(Z@W1 + b1)
    long long q = T / 4;
    k_self    <<<(int)((q + 255) / 256), 256>>>(N, 0);
    k_edge_agg<<<(E + 7) / 8, 256>>>(srcp, dstp, E, 0);
    {
        dim3 g(DH / 128, (N + 127) / 128);
        k_gemm<<<g, 256>>>(W1, b1, nullptr, N, DH, 1);
    }

    // layer 2: Z = agg(h); mu/logstd = Z@W{mu,ls} + b
    k_self    <<<(int)((q + 255) / 256), 256>>>(N, 1);
    k_edge_agg<<<(E + 7) / 8, 256>>>(srcp, dstp, E, 1);
    {
        dim3 g(DOUT / 128, (N + 127) / 128);
        k_gemm<<<g, 256>>>(Wmu, bmu, out, N, DOUT, 0);
        k_gemm<<<g, 256>>>(Wls, bls, out + (size_t)N * DOUT, N, DOUT, 0);
    }
}

// round 4
// speedup vs baseline: 1.8961x; 1.8961x over previous
#include <cuda_runtime.h>
#include <cstdint>

// ---------------------------------------------------------------------------
// VGAE/GCN encoder, round 4: CSR aggregation, device-global pointers resolved
// in device code only (R3 bug: host-side __device__ symbol decays to host
// shadow address; GB300 ATS reads host zeros silently).
// ---------------------------------------------------------------------------

#define NN 50000
#define EE 800000
#define DH 512
#define DOUT 256

__device__ float g_Xd[(size_t)NN * DH];   // dropout(x)
__device__ float g_Z [(size_t)NN * DH];   // aggregation output
__device__ float g_h [(size_t)NN * DH];   // hidden activations
__device__ float g_dinv[NN];
__device__ int   g_deg[NN];
__device__ int   g_rowptr[NN + 1];
__device__ int   g_cursor[NN];
__device__ int   g_csrc[EE];              // src ids sorted by dst
__device__ float g_cw[EE];                // per-edge weight dinv[s]*dinv[d]

// ----------------------------- threefry2x32 --------------------------------
__device__ __forceinline__ uint32_t rotl32(uint32_t v, int r) {
    return (v << r) | (v >> (32 - r));
}

__device__ __forceinline__ void threefry2x32(uint32_t k0, uint32_t k1,
                                             uint32_t& x0, uint32_t& x1) {
    uint32_t ks2 = 0x1BD11BDAu ^ k0 ^ k1;
    x0 += k0; x1 += k1;
#define TFR(r) { x0 += x1; x1 = rotl32(x1, r); x1 ^= x0; }
    TFR(13) TFR(15) TFR(26) TFR(6)
    x0 += k1;  x1 += ks2 + 1u;
    TFR(17) TFR(29) TFR(16) TFR(24)
    x0 += ks2; x1 += k0 + 2u;
    TFR(13) TFR(15) TFR(26) TFR(6)
    x0 += k0;  x1 += k1 + 3u;
    TFR(17) TFR(29) TFR(16) TFR(24)
    x0 += k1;  x1 += ks2 + 4u;
    TFR(13) TFR(15) TFR(26) TFR(6)
    x0 += ks2; x1 += k0 + 5u;
#undef TFR
}

// ----------------------------- graph prep ----------------------------------
__global__ void k_deg_init(int n) {
    int i = blockIdx.x * blockDim.x + threadIdx.x;
    if (i < n) g_deg[i] = 0;
}

__global__ void k_deg_accum(const int* __restrict__ dst, int E) {
    int e = blockIdx.x * blockDim.x + threadIdx.x;
    if (e < E) atomicAdd(&g_deg[dst[e]], 1);
}

__global__ void k_deg_finish(int n) {
    int i = blockIdx.x * blockDim.x + threadIdx.x;
    if (i < n) g_dinv[i] = rsqrtf((float)g_deg[i] + 1.0f);
}

// Single-block exclusive scan of g_deg -> g_rowptr, g_cursor.
__global__ void k_scan(int n) {
    __shared__ int sh[1024];
    __shared__ int carry;
    int tid = threadIdx.x;
    if (tid == 0) carry = 0;
    __syncthreads();
    for (int base = 0; base < n; base += 1024) {
        int i = base + tid;
        int v = (i < n) ? g_deg[i] : 0;
        sh[tid] = v;
        __syncthreads();
#pragma unroll
        for (int off = 1; off < 1024; off <<= 1) {
            int t = (tid >= off) ? sh[tid - off] : 0;
            __syncthreads();
            sh[tid] += t;
            __syncthreads();
        }
        int c = carry;
        if (i < n) {
            int excl = c + sh[tid] - v;
            g_rowptr[i] = excl;
            g_cursor[i] = excl;
        }
        __syncthreads();
        if (tid == 0) carry = c + sh[1023];
        __syncthreads();
    }
    if (tid == 0) g_rowptr[n] = carry;
}

__global__ void k_scatter(const int* __restrict__ src,
                          const int* __restrict__ dst, int E) {
    int e = blockIdx.x * blockDim.x + threadIdx.x;
    if (e >= E) return;
    int s = src[e];
    int d = dst[e];
    int pos = atomicAdd(&g_cursor[d], 1);
    g_csrc[pos] = s;
    g_cw[pos] = g_dinv[s] * g_dinv[d];
}

// ------------------------------ dropout ------------------------------------
__global__ void k_dropout(const float* __restrict__ x, long long T) {
    long long i = (long long)blockIdx.x * blockDim.x + threadIdx.x;
    if (i >= T) return;
    uint32_t hi = 0u;
    uint32_t lo = (uint32_t)i;
    threefry2x32(0u, 42u, hi, lo);
    uint32_t bits = hi ^ lo;     // partitionable 32-bit: b1 ^ b2
    float u = __uint_as_float((bits >> 9) | 0x3f800000u) - 1.0f;
    g_Xd[i] = (u < 0.5f) ? x[i] * 2.0f : 0.0f;
}

// ------------------------- CSR aggregation ---------------------------------
// One block (128 threads) per node. which: 0 -> g_Xd, 1 -> g_h (resolved in
// DEVICE code — never pass __device__ symbols from host!).
__global__ __launch_bounds__(128)
void k_agg(int which) {
    int node = blockIdx.x;
    int tid  = threadIdx.x;
    const float4* X4 = (const float4*)(which ? g_h : g_Xd);
    float dv = g_dinv[node];
    float w0 = dv * dv;
    float4 a = X4[(size_t)node * 128 + tid];
    float4 acc = make_float4(a.x * w0, a.y * w0, a.z * w0, a.w * w0);
    int e0 = g_rowptr[node];
    int e1 = g_rowptr[node + 1];
    for (int e = e0; e < e1; e++) {
        int   s = g_csrc[e];
        float w = g_cw[e];
        float4 v = X4[(size_t)s * 128 + tid];
        acc.x += v.x * w;
        acc.y += v.y * w;
        acc.z += v.z * w;
        acc.w += v.w * w;
    }
    ((float4*)g_Z)[(size_t)node * 128 + tid] = acc;
}

// ------------------------------- SGEMM -------------------------------------
__global__ __launch_bounds__(256, 2)
void k_gemm(const float* __restrict__ B, const float* __restrict__ bias,
            float* __restrict__ Cext, int M, int Ncols, int relu) {
    const int K = 512;
    __shared__ float As[8][128];
    __shared__ float Bs[8][128];
    int tid = threadIdx.x;
    int tx = tid & 15, ty = tid >> 4;
    int rowBase = blockIdx.y * 128;
    int colBase = blockIdx.x * 128;
    float acc[8][8];
#pragma unroll
    for (int i = 0; i < 8; i++)
#pragma unroll
        for (int j = 0; j < 8; j++) acc[i][j] = 0.0f;

    int aRow = tid >> 1, aCol = (tid & 1) * 4;
    int bRow = tid >> 5, bCol = (tid & 31) * 4;
    const float* A = g_Z;

    for (int k0 = 0; k0 < K; k0 += 8) {
        float4 av = make_float4(0.f, 0.f, 0.f, 0.f);
        int ar = rowBase + aRow;
        if (ar < M)
            av = *(const float4*)(A + (size_t)ar * K + k0 + aCol);
        As[aCol + 0][aRow] = av.x;
        As[aCol + 1][aRow] = av.y;
        As[aCol + 2][aRow] = av.z;
        As[aCol + 3][aRow] = av.w;
        float4 bv = *(const float4*)(B + (size_t)(k0 + bRow) * Ncols + colBase + bCol);
        *(float4*)&Bs[bRow][bCol] = bv;
        __syncthreads();
#pragma unroll
        for (int k = 0; k < 8; k++) {
            float a8[8], b8[8];
#pragma unroll
            for (int i = 0; i < 8; i++) a8[i] = As[k][ty * 8 + i];
#pragma unroll
            for (int j = 0; j < 8; j++) b8[j] = Bs[k][tx * 8 + j];
#pragma unroll
            for (int i = 0; i < 8; i++)
#pragma unroll
                for (int j = 0; j < 8; j++) acc[i][j] += a8[i] * b8[j];
        }
        __syncthreads();
    }

    float bv[8];
#pragma unroll
    for (int j = 0; j < 8; j++) bv[j] = bias[colBase + tx * 8 + j];
    float* Cw = relu ? g_h : Cext;
#pragma unroll
    for (int i = 0; i < 8; i++) {
        int r = rowBase + ty * 8 + i;
        if (r < M) {
#pragma unroll
            for (int j = 0; j < 8; j++) {
                float v = acc[i][j] + bv[j];
                if (relu) v = fmaxf(v, 0.0f);
                Cw[(size_t)r * Ncols + colBase + tx * 8 + j] = v;
            }
        }
    }
}

// ------------------------------- launch ------------------------------------
extern "C" void kernel_launch(void* const* d_in, const int* in_sizes, int n_in,
                              void* d_out, int out_size) {
    const float* x   = (const float*)d_in[0];
    const int*   ei  = (const int*)d_in[1];     // int32 (JAX x64 disabled)
    const float* W1  = (const float*)d_in[2];
    const float* b1  = (const float*)d_in[3];
    const float* Wmu = (const float*)d_in[4];
    const float* bmu = (const float*)d_in[5];
    const float* Wls = (const float*)d_in[6];
    const float* bls = (const float*)d_in[7];
    float* out = (float*)d_out;

    int N = in_sizes[0] / DH;
    int E = in_sizes[1] / 2;
    const int* srcp = ei;
    const int* dstp = ei + E;
    long long T = (long long)N * DH;

    // graph prep: degrees -> dinv -> CSR
    k_deg_init  <<<(N + 255) / 256, 256>>>(N);
    k_deg_accum <<<(E + 255) / 256, 256>>>(dstp, E);
    k_deg_finish<<<(N + 255) / 256, 256>>>(N);
    k_scan      <<<1, 1024>>>(N);
    k_scatter   <<<(E + 255) / 256, 256>>>(srcp, dstp, E);

    // dropout
    k_dropout<<<(int)((T + 255) / 256), 256>>>(x, T);

    // layer 1
    k_agg<<<N, 128>>>(0);
    {
        dim3 g(DH / 128, (N + 127) / 128);
        k_gemm<<<g, 256>>>(W1, b1, nullptr, N, DH, 1);
    }

    // layer 2
    k_agg<<<N, 128>>>(1);
    {
        dim3 g(DOUT / 128, (N + 127) / 128);
        k_gemm<<<g, 256>>>(Wmu, bmu, out, N, DOUT, 0);
        k_gemm<<<g, 256>>>(Wls, bls, out + (size_t)N * DOUT, N, DOUT, 0);
    }
}

// round 7
// speedup vs baseline: 3.3850x; 1.7852x over previous
#include <cuda_runtime.h>
#include <cuda_bf16.h>
#include <cstdint>

// ---------------------------------------------------------------------------
// VGAE/GCN encoder, round 6: bf16-split (3-pass) mma.sync GEMMs + CSR agg.
// tcgen05 is unavailable: harness compiles for base sm_103 target (no 'a').
// ---------------------------------------------------------------------------

#define NN 50000
#define EE 800000
#define DH 512

__device__ __align__(16) float g_Xd[(size_t)NN * DH];
__device__ __align__(16) float g_h [(size_t)NN * DH];
__device__ __align__(16) __nv_bfloat16 g_Zh[(size_t)NN * DH];
__device__ __align__(16) __nv_bfloat16 g_Zl[(size_t)NN * DH];
__device__ __align__(16) __nv_bfloat16 g_W1h[512 * 512];   // [N][K]
__device__ __align__(16) __nv_bfloat16 g_W1l[512 * 512];
__device__ __align__(16) __nv_bfloat16 g_W2h[512 * 512];   // fused [Wmu|Wls]
__device__ __align__(16) __nv_bfloat16 g_W2l[512 * 512];
__device__ float g_bias2[512];
__device__ float g_dinv[NN];
__device__ int   g_deg[NN];
__device__ int   g_rowptr[NN + 1];
__device__ int   g_cursor[NN];
__device__ int   g_csrc[EE];
__device__ float g_cw[EE];

// ----------------------------- threefry2x32 --------------------------------
__device__ __forceinline__ uint32_t rotl32(uint32_t v, int r) {
    return (v << r) | (v >> (32 - r));
}

__device__ __forceinline__ void threefry2x32(uint32_t k0, uint32_t k1,
                                             uint32_t& x0, uint32_t& x1) {
    uint32_t ks2 = 0x1BD11BDAu ^ k0 ^ k1;
    x0 += k0; x1 += k1;
#define TFR(r) { x0 += x1; x1 = rotl32(x1, r); x1 ^= x0; }
    TFR(13) TFR(15) TFR(26) TFR(6)
    x0 += k1;  x1 += ks2 + 1u;
    TFR(17) TFR(29) TFR(16) TFR(24)
    x0 += ks2; x1 += k0 + 2u;
    TFR(13) TFR(15) TFR(26) TFR(6)
    x0 += k0;  x1 += k1 + 3u;
    TFR(17) TFR(29) TFR(16) TFR(24)
    x0 += k1;  x1 += ks2 + 4u;
    TFR(13) TFR(15) TFR(26) TFR(6)
    x0 += ks2; x1 += k0 + 5u;
#undef TFR
}

// ----------------------------- graph prep ----------------------------------
__global__ void k_deg_init(int n) {
    int i = blockIdx.x * blockDim.x + threadIdx.x;
    if (i < n) g_deg[i] = 0;
}

__global__ void k_deg_accum(const int* __restrict__ dst, int E) {
    int e = blockIdx.x * blockDim.x + threadIdx.x;
    if (e < E) atomicAdd(&g_deg[dst[e]], 1);
}

__global__ void k_deg_finish(int n) {
    int i = blockIdx.x * blockDim.x + threadIdx.x;
    if (i < n) g_dinv[i] = rsqrtf((float)g_deg[i] + 1.0f);
}

// 1024-thread two-level scan: serial chunks + shfl block scan.
__global__ void k_scan(int n) {
    __shared__ int wsum[32];
    int tid = threadIdx.x, lane = tid & 31, w = tid >> 5;
    const int CH = (NN + 1023) / 1024;
    int base = tid * CH;
    int sum = 0;
    for (int i = 0; i < CH; i++) {
        int idx = base + i;
        if (idx < n) sum += g_deg[idx];
    }
    int x = sum;
#pragma unroll
    for (int o = 1; o < 32; o <<= 1) {
        int t = __shfl_up_sync(0xffffffffu, x, o);
        if (lane >= o) x += t;
    }
    if (lane == 31) wsum[w] = x;
    __syncthreads();
    if (w == 0) {
        int y = wsum[lane];
        int z = y;
#pragma unroll
        for (int o = 1; o < 32; o <<= 1) {
            int t = __shfl_up_sync(0xffffffffu, z, o);
            if (lane >= o) z += t;
        }
        wsum[lane] = z - y;
    }
    __syncthreads();
    int run = wsum[w] + (x - sum);
    for (int i = 0; i < CH; i++) {
        int idx = base + i;
        if (idx < n) {
            g_rowptr[idx] = run;
            g_cursor[idx] = run;
            run += g_deg[idx];
        }
    }
    if (tid == 1023) g_rowptr[n] = run;
}

__global__ void k_scatter(const int* __restrict__ src,
                          const int* __restrict__ dst, int E) {
    int e = blockIdx.x * blockDim.x + threadIdx.x;
    if (e >= E) return;
    int s = src[e];
    int d = dst[e];
    int pos = atomicAdd(&g_cursor[d], 1);
    g_csrc[pos] = s;
    g_cw[pos] = g_dinv[s] * g_dinv[d];
}

// ------------------------------ dropout ------------------------------------
__global__ void k_dropout(const float* __restrict__ x, long long T) {
    long long i = (long long)blockIdx.x * blockDim.x + threadIdx.x;
    if (i >= T) return;
    uint32_t hi = 0u;
    uint32_t lo = (uint32_t)i;
    threefry2x32(0u, 42u, hi, lo);
    uint32_t bits = hi ^ lo;
    float u = __uint_as_float((bits >> 9) | 0x3f800000u) - 1.0f;
    g_Xd[i] = (u < 0.5f) ? x[i] * 2.0f : 0.0f;
}

// --------------------------- weight prep -----------------------------------
__device__ __forceinline__ void bf16split(float w, __nv_bfloat16& h, __nv_bfloat16& l) {
    h = __float2bfloat16_rn(w);
    l = __float2bfloat16_rn(w - __bfloat162float(h));
}

__global__ void k_wprep1(const float* __restrict__ W1) {
    int idx = blockIdx.x * blockDim.x + threadIdx.x;
    if (idx >= 512 * 512) return;
    int n = idx >> 9, k = idx & 511;
    bf16split(W1[k * 512 + n], g_W1h[idx], g_W1l[idx]);
}

__global__ void k_wprep2(const float* __restrict__ Wmu, const float* __restrict__ Wls,
                         const float* __restrict__ bmu, const float* __restrict__ bls) {
    int idx = blockIdx.x * blockDim.x + threadIdx.x;
    if (idx >= 512 * 512) return;
    int n = idx >> 9, k = idx & 511;
    float w = (n < 256) ? Wmu[k * 256 + n] : Wls[k * 256 + (n - 256)];
    bf16split(w, g_W2h[idx], g_W2l[idx]);
    if (idx < 512) g_bias2[idx] = (idx < 256) ? bmu[idx] : bls[idx - 256];
}

// ------------------------- CSR aggregation ---------------------------------
// One block per node; writes bf16 hi/lo split. which: 0 -> g_Xd, 1 -> g_h.
__global__ __launch_bounds__(128)
void k_agg(int which) {
    int node = blockIdx.x;
    int tid  = threadIdx.x;
    const float4* X4 = (const float4*)(which ? g_h : g_Xd);
    float dv = g_dinv[node];
    float w0 = dv * dv;
    float4 a = X4[(size_t)node * 128 + tid];
    float4 acc = make_float4(a.x * w0, a.y * w0, a.z * w0, a.w * w0);
    int e0 = g_rowptr[node];
    int e1 = g_rowptr[node + 1];
    for (int e = e0; e < e1; e++) {
        int   s = g_csrc[e];
        float w = g_cw[e];
        float4 v = X4[(size_t)s * 128 + tid];
        acc.x += v.x * w;
        acc.y += v.y * w;
        acc.z += v.z * w;
        acc.w += v.w * w;
    }
    __nv_bfloat16 hx, lx, hy, ly, hz, lz, hw, lw;
    bf16split(acc.x, hx, lx);
    bf16split(acc.y, hy, ly);
    bf16split(acc.z, hz, lz);
    bf16split(acc.w, hw, lw);
    __nv_bfloat162* Zh2 = (__nv_bfloat162*)g_Zh;
    __nv_bfloat162* Zl2 = (__nv_bfloat162*)g_Zl;
    size_t o = (size_t)node * 256 + tid * 2;
    Zh2[o]     = __nv_bfloat162(hx, hy);
    Zh2[o + 1] = __nv_bfloat162(hz, hw);
    Zl2[o]     = __nv_bfloat162(lx, ly);
    Zl2[o + 1] = __nv_bfloat162(lz, lw);
}

// --------------------------- tensor GEMM -----------------------------------
// C[M,512] = (Zh+Zl) @ (Wh+Wl)^T, 3-pass bf16 split via mma.sync m16n8k16.
// Block 128x128, 8 warps (4M x 2N), warp 32x64, K staged 32 w/ cp.async x2.
// mode 0: +b1, relu -> g_h (W1). mode 1: +g_bias2 -> out mu|logstd (W2).
#define RSTRIDE 20                       // u32 per 32-bf16 row (padded)
#define MAT_U32 (128 * RSTRIDE)          // 2560
#define BUF_U32 (4 * MAT_U32)            // 10240
#define SMEM_GEMM (2 * BUF_U32 * 4)      // 81920 bytes

__device__ __forceinline__ void mma16816(float* c, const uint32_t* a, const uint32_t* b) {
    asm volatile(
        "mma.sync.aligned.m16n8k16.row.col.f32.bf16.bf16.f32 "
        "{%0,%1,%2,%3}, {%4,%5,%6,%7}, {%8,%9}, {%0,%1,%2,%3};"
        : "+f"(c[0]), "+f"(c[1]), "+f"(c[2]), "+f"(c[3])
        : "r"(a[0]), "r"(a[1]), "r"(a[2]), "r"(a[3]), "r"(b[0]), "r"(b[1]));
}

__device__ __forceinline__ void cpa16(uint32_t dst, const void* src) {
    asm volatile("cp.async.cg.shared.global [%0], [%1], 16;"
                 :: "r"(dst), "l"(src) : "memory");
}

__global__ __launch_bounds__(256, 1)
void k_tgemm(const float* __restrict__ bias0, float* __restrict__ outp, int mode) {
    extern __shared__ __align__(16) uint32_t smem[];
    uint32_t sb;
    asm("{ .reg .u64 t; cvta.to.shared.u64 t, %1; cvt.u32.u64 %0, t; }"
        : "=r"(sb) : "l"(smem));

    int tid = threadIdx.x, lane = tid & 31;
    int warpId = tid >> 5;
    int warpM = warpId & 3, warpN = warpId >> 2;
    int mBase = blockIdx.y * 128;
    int nBase = blockIdx.x * 128;

    const __nv_bfloat16* Ah = g_Zh;
    const __nv_bfloat16* Al = g_Zl;
    const __nv_bfloat16* Bh = mode ? g_W2h : g_W1h;
    const __nv_bfloat16* Bl = mode ? g_W2l : g_W1l;

    float acc[2][8][4];
#pragma unroll
    for (int i = 0; i < 2; i++)
#pragma unroll
        for (int j = 0; j < 8; j++)
#pragma unroll
            for (int c = 0; c < 4; c++) acc[i][j][c] = 0.0f;

    // per-thread load coords (2 chunks of 16B per matrix per tile)
    int ck0 = tid * 2, ck1 = tid * 2 + 1;
    int r0 = ck0 >> 2, q0 = (ck0 & 3);
    int r1 = ck1 >> 2, q1 = (ck1 & 3);
    int ar0 = min(mBase + r0, NN - 1);
    int ar1 = min(mBase + r1, NN - 1);
    int br0 = nBase + r0, br1 = nBase + r1;
    uint32_t d0 = sb + (r0 * RSTRIDE + q0 * 4) * 4;
    uint32_t d1 = sb + (r1 * RSTRIDE + q1 * 4) * 4;

    auto load_tile = [&](int t, int buf) {
        int k0 = t * 32;
        uint32_t bo = buf * BUF_U32 * 4;
        size_t a0o = (size_t)ar0 * 512 + k0 + q0 * 8;
        size_t a1o = (size_t)ar1 * 512 + k0 + q1 * 8;
        size_t b0o = (size_t)br0 * 512 + k0 + q0 * 8;
        size_t b1o = (size_t)br1 * 512 + k0 + q1 * 8;
        cpa16(d0 + bo,                Ah + a0o);
        cpa16(d1 + bo,                Ah + a1o);
        cpa16(d0 + bo + MAT_U32 * 4,  Al + a0o);
        cpa16(d1 + bo + MAT_U32 * 4,  Al + a1o);
        cpa16(d0 + bo + MAT_U32 * 8,  Bh + b0o);
        cpa16(d1 + bo + MAT_U32 * 8,  Bh + b1o);
        cpa16(d0 + bo + MAT_U32 * 12, Bl + b0o);
        cpa16(d1 + bo + MAT_U32 * 12, Bl + b1o);
        asm volatile("cp.async.commit_group;" ::: "memory");
    };

    load_tile(0, 0);
    int cur = 0;

    for (int t = 0; t < 16; t++) {
        if (t + 1 < 16) {
            load_tile(t + 1, cur ^ 1);
            asm volatile("cp.async.wait_group 1;" ::: "memory");
        } else {
            asm volatile("cp.async.wait_group 0;" ::: "memory");
        }
        __syncthreads();

        const uint32_t* SAh = smem + cur * BUF_U32;
        const uint32_t* SAl = SAh + MAT_U32;
        const uint32_t* SBh = SAl + MAT_U32;
        const uint32_t* SBl = SBh + MAT_U32;

#pragma unroll
        for (int ks = 0; ks < 2; ks++) {
            uint32_t aH[2][4], aL[2][4];
#pragma unroll
            for (int mt = 0; mt < 2; mt++) {
                int row = warpM * 32 + mt * 16 + (lane >> 2);
                int ib = row * RSTRIDE + ks * 8 + (lane & 3);
                aH[mt][0] = SAh[ib];
                aH[mt][1] = SAh[ib + 8 * RSTRIDE];
                aH[mt][2] = SAh[ib + 4];
                aH[mt][3] = SAh[ib + 8 * RSTRIDE + 4];
                aL[mt][0] = SAl[ib];
                aL[mt][1] = SAl[ib + 8 * RSTRIDE];
                aL[mt][2] = SAl[ib + 4];
                aL[mt][3] = SAl[ib + 8 * RSTRIDE + 4];
            }
            uint32_t bH[8][2], bL[8][2];
#pragma unroll
            for (int nt = 0; nt < 8; nt++) {
                int row = warpN * 64 + nt * 8 + (lane >> 2);
                int ib = row * RSTRIDE + ks * 8 + (lane & 3);
                bH[nt][0] = SBh[ib];
                bH[nt][1] = SBh[ib + 4];
                bL[nt][0] = SBl[ib];
                bL[nt][1] = SBl[ib + 4];
            }
#pragma unroll
            for (int mt = 0; mt < 2; mt++)
#pragma unroll
                for (int nt = 0; nt < 8; nt++) {
                    mma16816(acc[mt][nt], aH[mt], bH[nt]);
                    mma16816(acc[mt][nt], aH[mt], bL[nt]);
                    mma16816(acc[mt][nt], aL[mt], bH[nt]);
                }
        }
        __syncthreads();
        cur ^= 1;
    }

    // epilogue
    const float* bias = mode ? g_bias2 : bias0;
#pragma unroll
    for (int mt = 0; mt < 2; mt++) {
#pragma unroll
        for (int nt = 0; nt < 8; nt++) {
            int r = mBase + warpM * 32 + mt * 16 + (lane >> 2);
            int c = nBase + warpN * 64 + nt * 8 + 2 * (lane & 3);
            float b0 = bias[c], b1v = bias[c + 1];
            float v0 = acc[mt][nt][0] + b0;
            float v1 = acc[mt][nt][1] + b1v;
            float v2 = acc[mt][nt][2] + b0;
            float v3 = acc[mt][nt][3] + b1v;
            if (mode == 0) {
                v0 = fmaxf(v0, 0.0f); v1 = fmaxf(v1, 0.0f);
                v2 = fmaxf(v2, 0.0f); v3 = fmaxf(v3, 0.0f);
            }
            if (mode == 0) {
                if (r < NN)     *(float2*)(g_h + (size_t)r * 512 + c)       = make_float2(v0, v1);
                if (r + 8 < NN) *(float2*)(g_h + (size_t)(r + 8) * 512 + c) = make_float2(v2, v3);
            } else {
                size_t half = (c < 256) ? 0 : (size_t)NN * 256;
                int cc = (c < 256) ? c : c - 256;
                if (r < NN)     *(float2*)(outp + half + (size_t)r * 256 + cc)       = make_float2(v0, v1);
                if (r + 8 < NN) *(float2*)(outp + half + (size_t)(r + 8) * 256 + cc) = make_float2(v2, v3);
            }
        }
    }
}

// ------------------------------- launch ------------------------------------
extern "C" void kernel_launch(void* const* d_in, const int* in_sizes, int n_in,
                              void* d_out, int out_size) {
    const float* x   = (const float*)d_in[0];
    const int*   ei  = (const int*)d_in[1];
    const float* W1  = (const float*)d_in[2];
    const float* b1  = (const float*)d_in[3];
    const float* Wmu = (const float*)d_in[4];
    const float* bmu = (const float*)d_in[5];
    const float* Wls = (const float*)d_in[6];
    const float* bls = (const float*)d_in[7];
    float* out = (float*)d_out;

    int N = in_sizes[0] / DH;
    int E = in_sizes[1] / 2;
    const int* srcp = ei;
    const int* dstp = ei + E;
    long long T = (long long)N * DH;

    static bool s_init = false;
    if (!s_init) {
        cudaFuncSetAttribute(k_tgemm, cudaFuncAttributeMaxDynamicSharedMemorySize,
                             SMEM_GEMM);
        s_init = true;
    }

    // graph prep
    k_deg_init  <<<(N + 255) / 256, 256>>>(N);
    k_deg_accum <<<(E + 255) / 256, 256>>>(dstp, E);
    k_deg_finish<<<(N + 255) / 256, 256>>>(N);
    k_scan      <<<1, 1024>>>(N);
    k_scatter   <<<(E + 255) / 256, 256>>>(srcp, dstp, E);

    // dropout + weight prep
    k_dropout<<<(int)((T + 255) / 256), 256>>>(x, T);
    k_wprep1 <<<(512 * 512 + 255) / 256, 256>>>(W1);
    k_wprep2 <<<(512 * 512 + 255) / 256, 256>>>(Wmu, Wls, bmu, bls);

    dim3 gmm(4, (N + 127) / 128);

    // layer 1
    k_agg<<<N, 128>>>(0);
    k_tgemm<<<gmm, 256, SMEM_GEMM>>>(b1, nullptr, 0);

    // layer 2 (fused mu | logstd)
    k_agg<<<N, 128>>>(1);
    k_tgemm<<<gmm, 256, SMEM_GEMM>>>(b1, out, 1);
}

// round 8
// speedup vs baseline: 3.4821x; 1.0287x over previous
#include <cuda_runtime.h>
#include <cuda_bf16.h>
#include <cstdint>

// ---------------------------------------------------------------------------
// VGAE/GCN encoder, round 8: bf16-split mma.sync GEMM w/ ldmatrix, coalesced
// tiled scan (+fused dinv), fused prep kernel (deg_accum|dropout|wprep).
// ---------------------------------------------------------------------------

#define NN 50000
#define EE 800000
#define DH 512

__device__ __align__(16) float g_Xd[(size_t)NN * DH];
__device__ __align__(16) float g_h [(size_t)NN * DH];
__device__ __align__(16) __nv_bfloat16 g_Zh[(size_t)NN * DH];
__device__ __align__(16) __nv_bfloat16 g_Zl[(size_t)NN * DH];
__device__ __align__(16) __nv_bfloat16 g_W1h[512 * 512];   // [N][K]
__device__ __align__(16) __nv_bfloat16 g_W1l[512 * 512];
__device__ __align__(16) __nv_bfloat16 g_W2h[512 * 512];   // fused [Wmu|Wls]
__device__ __align__(16) __nv_bfloat16 g_W2l[512 * 512];
__device__ float g_bias2[512];
__device__ float g_dinv[NN];
__device__ int   g_deg[NN];
__device__ int   g_rowptr[NN + 1];
__device__ int   g_cursor[NN];
__device__ int   g_csrc[EE];
__device__ float g_cw[EE];

// ----------------------------- threefry2x32 --------------------------------
__device__ __forceinline__ uint32_t rotl32(uint32_t v, int r) {
    return (v << r) | (v >> (32 - r));
}

__device__ __forceinline__ void threefry2x32(uint32_t k0, uint32_t k1,
                                             uint32_t& x0, uint32_t& x1) {
    uint32_t ks2 = 0x1BD11BDAu ^ k0 ^ k1;
    x0 += k0; x1 += k1;
#define TFR(r) { x0 += x1; x1 = rotl32(x1, r); x1 ^= x0; }
    TFR(13) TFR(15) TFR(26) TFR(6)
    x0 += k1;  x1 += ks2 + 1u;
    TFR(17) TFR(29) TFR(16) TFR(24)
    x0 += ks2; x1 += k0 + 2u;
    TFR(13) TFR(15) TFR(26) TFR(6)
    x0 += k0;  x1 += k1 + 3u;
    TFR(17) TFR(29) TFR(16) TFR(24)
    x0 += k1;  x1 += ks2 + 4u;
    TFR(13) TFR(15) TFR(26) TFR(6)
    x0 += ks2; x1 += k0 + 5u;
#undef TFR
}

__device__ __forceinline__ void bf16split(float w, __nv_bfloat16& h, __nv_bfloat16& l) {
    h = __float2bfloat16_rn(w);
    l = __float2bfloat16_rn(w - __bfloat162float(h));
}

// ----------------------------- graph prep ----------------------------------
__global__ void k_deg_init(int n) {
    int i = blockIdx.x * blockDim.x + threadIdx.x;
    if (i < n) g_deg[i] = 0;
}

// Fused independent prep: [deg_accum | wprep1 | wprep2 | dropout], by block.
__global__ void k_prep(const float* __restrict__ x, const int* __restrict__ dst,
                       const float* __restrict__ W1,
                       const float* __restrict__ Wmu, const float* __restrict__ Wls,
                       const float* __restrict__ bmu, const float* __restrict__ bls,
                       int E, long long T, int nbE, int nbW) {
    int b = blockIdx.x;
    int tid = threadIdx.x;
    if (b < nbE) {                                   // degree atomics
        int e = b * 256 + tid;
        if (e < E) atomicAdd(&g_deg[dst[e]], 1);
        return;
    }
    b -= nbE;
    if (b < nbW) {                                   // wprep1
        int idx = b * 256 + tid;
        int n = idx >> 9, k = idx & 511;
        bf16split(W1[k * 512 + n], g_W1h[idx], g_W1l[idx]);
        return;
    }
    b -= nbW;
    if (b < nbW) {                                   // wprep2 (+bias concat)
        int idx = b * 256 + tid;
        int n = idx >> 9, k = idx & 511;
        float w = (n < 256) ? Wmu[k * 256 + n] : Wls[k * 256 + (n - 256)];
        bf16split(w, g_W2h[idx], g_W2l[idx]);
        if (idx < 512) g_bias2[idx] = (idx < 256) ? bmu[idx] : bls[idx - 256];
        return;
    }
    b -= nbW;
    long long i = (long long)b * 256 + tid;          // dropout
    if (i >= T) return;
    uint32_t hi = 0u;
    uint32_t lo = (uint32_t)i;
    threefry2x32(0u, 42u, hi, lo);
    uint32_t bits = hi ^ lo;
    float u = __uint_as_float((bits >> 9) | 0x3f800000u) - 1.0f;
    g_Xd[i] = (u < 0.5f) ? x[i] * 2.0f : 0.0f;
}

// Tiled coalesced scan with carry; also writes g_dinv (fuses deg_finish).
__global__ void k_scan(int n) {
    __shared__ int wsum[32];
    __shared__ int s_carry;
    int tid = threadIdx.x, lane = tid & 31, w = tid >> 5;
    if (tid == 0) s_carry = 0;
    __syncthreads();
    for (int base = 0; base < n; base += 1024) {
        int i = base + tid;
        int v = (i < n) ? g_deg[i] : 0;
        if (i < n) g_dinv[i] = rsqrtf((float)v + 1.0f);
        int x = v;
#pragma unroll
        for (int o = 1; o < 32; o <<= 1) {
            int t = __shfl_up_sync(0xffffffffu, x, o);
            if (lane >= o) x += t;
        }
        if (lane == 31) wsum[w] = x;
        __syncthreads();
        if (w == 0) {
            int y = wsum[lane];
            int z = y;
#pragma unroll
            for (int o = 1; o < 32; o <<= 1) {
                int t = __shfl_up_sync(0xffffffffu, z, o);
                if (lane >= o) z += t;
            }
            wsum[lane] = z;                          // inclusive warp prefix
        }
        __syncthreads();
        int warpoff = (w == 0) ? 0 : wsum[w - 1];
        int c = s_carry;
        int excl = c + warpoff + x - v;
        if (i < n) {
            g_rowptr[i] = excl;
            g_cursor[i] = excl;
        }
        int total = wsum[31];
        __syncthreads();
        if (tid == 0) s_carry = c + total;
        __syncthreads();
    }
    if (tid == 0) g_rowptr[n] = s_carry;
}

__global__ void k_scatter(const int* __restrict__ src,
                          const int* __restrict__ dst, int E) {
    int e = blockIdx.x * blockDim.x + threadIdx.x;
    if (e >= E) return;
    int s = src[e];
    int d = dst[e];
    int pos = atomicAdd(&g_cursor[d], 1);
    g_csrc[pos] = s;
    g_cw[pos] = g_dinv[s] * g_dinv[d];
}

// ------------------------- CSR aggregation ---------------------------------
__global__ __launch_bounds__(128)
void k_agg(int which) {
    int node = blockIdx.x;
    int tid  = threadIdx.x;
    const float4* X4 = (const float4*)(which ? g_h : g_Xd);
    float dv = g_dinv[node];
    float w0 = dv * dv;
    float4 a = X4[(size_t)node * 128 + tid];
    float4 acc = make_float4(a.x * w0, a.y * w0, a.z * w0, a.w * w0);
    int e0 = g_rowptr[node];
    int e1 = g_rowptr[node + 1];
    for (int e = e0; e < e1; e++) {
        int   s = g_csrc[e];
        float w = g_cw[e];
        float4 v = X4[(size_t)s * 128 + tid];
        acc.x += v.x * w;
        acc.y += v.y * w;
        acc.z += v.z * w;
        acc.w += v.w * w;
    }
    __nv_bfloat16 hx, lx, hy, ly, hz, lz, hw, lw;
    bf16split(acc.x, hx, lx);
    bf16split(acc.y, hy, ly);
    bf16split(acc.z, hz, lz);
    bf16split(acc.w, hw, lw);
    __nv_bfloat162* Zh2 = (__nv_bfloat162*)g_Zh;
    __nv_bfloat162* Zl2 = (__nv_bfloat162*)g_Zl;
    size_t o = (size_t)node * 256 + tid * 2;
    Zh2[o]     = __nv_bfloat162(hx, hy);
    Zh2[o + 1] = __nv_bfloat162(hz, hw);
    Zl2[o]     = __nv_bfloat162(lx, ly);
    Zl2[o + 1] = __nv_bfloat162(lz, lw);
}

// --------------------------- tensor GEMM -----------------------------------
#define RSTRIDE 20                       // u32 per 32-bf16 row (80 bytes)
#define MAT_U32 (128 * RSTRIDE)
#define BUF_U32 (4 * MAT_U32)
#define SMEM_GEMM (2 * BUF_U32 * 4)

__device__ __forceinline__ void mma16816(float* c, const uint32_t* a, const uint32_t* b) {
    asm volatile(
        "mma.sync.aligned.m16n8k16.row.col.f32.bf16.bf16.f32 "
        "{%0,%1,%2,%3}, {%4,%5,%6,%7}, {%8,%9}, {%0,%1,%2,%3};"
        : "+f"(c[0]), "+f"(c[1]), "+f"(c[2]), "+f"(c[3])
        : "r"(a[0]), "r"(a[1]), "r"(a[2]), "r"(a[3]), "r"(b[0]), "r"(b[1]));
}

__device__ __forceinline__ void cpa16(uint32_t dst, const void* src) {
    asm volatile("cp.async.cg.shared.global [%0], [%1], 16;"
                 :: "r"(dst), "l"(src) : "memory");
}

#define LDM4(r0, r1, r2, r3, a) \
    asm volatile("ldmatrix.sync.aligned.m8n8.x4.shared.b16 {%0,%1,%2,%3}, [%4];" \
                 : "=r"(r0), "=r"(r1), "=r"(r2), "=r"(r3) : "r"(a))

__global__ __launch_bounds__(256, 1)
void k_tgemm(const float* __restrict__ bias0, float* __restrict__ outp, int mode) {
    extern __shared__ __align__(16) uint32_t smem[];
    uint32_t sb;
    asm("{ .reg .u64 t; cvta.to.shared.u64 t, %1; cvt.u32.u64 %0, t; }"
        : "=r"(sb) : "l"(smem));

    int tid = threadIdx.x, lane = tid & 31;
    int warpId = tid >> 5;
    int warpM = warpId & 3, warpN = warpId >> 2;
    int mBase = blockIdx.y * 128;
    int nBase = blockIdx.x * 128;

    const __nv_bfloat16* Ah = g_Zh;
    const __nv_bfloat16* Al = g_Zl;
    const __nv_bfloat16* Bh = mode ? g_W2h : g_W1h;
    const __nv_bfloat16* Bl = mode ? g_W2l : g_W1l;

    float acc[2][8][4];
#pragma unroll
    for (int i = 0; i < 2; i++)
#pragma unroll
        for (int j = 0; j < 8; j++)
#pragma unroll
            for (int c = 0; c < 4; c++) acc[i][j][c] = 0.0f;

    int ck0 = tid * 2, ck1 = tid * 2 + 1;
    int r0 = ck0 >> 2, q0 = (ck0 & 3);
    int r1 = ck1 >> 2, q1 = (ck1 & 3);
    int ar0 = min(mBase + r0, NN - 1);
    int ar1 = min(mBase + r1, NN - 1);
    int br0 = nBase + r0, br1 = nBase + r1;
    uint32_t d0 = sb + (r0 * RSTRIDE + q0 * 4) * 4;
    uint32_t d1 = sb + (r1 * RSTRIDE + q1 * 4) * 4;

    auto load_tile = [&](int t, int buf) {
        int k0 = t * 32;
        uint32_t bo = buf * BUF_U32 * 4;
        size_t a0o = (size_t)ar0 * 512 + k0 + q0 * 8;
        size_t a1o = (size_t)ar1 * 512 + k0 + q1 * 8;
        size_t b0o = (size_t)br0 * 512 + k0 + q0 * 8;
        size_t b1o = (size_t)br1 * 512 + k0 + q1 * 8;
        cpa16(d0 + bo,                Ah + a0o);
        cpa16(d1 + bo,                Ah + a1o);
        cpa16(d0 + bo + MAT_U32 * 4,  Al + a0o);
        cpa16(d1 + bo + MAT_U32 * 4,  Al + a1o);
        cpa16(d0 + bo + MAT_U32 * 8,  Bh + b0o);
        cpa16(d1 + bo + MAT_U32 * 8,  Bh + b1o);
        cpa16(d0 + bo + MAT_U32 * 12, Bl + b0o);
        cpa16(d1 + bo + MAT_U32 * 12, Bl + b1o);
        asm volatile("cp.async.commit_group;" ::: "memory");
    };

    load_tile(0, 0);
    int cur = 0;

    // ldmatrix lane address components (bytes within a matrix)
    int aRowOff = (warpM * 32 + (lane & 15)) * 80 + ((lane >> 4) << 4);
    int bRowOff = (warpN * 64 + ((lane >> 4) << 3) + (lane & 7)) * 80
                  + (((lane >> 3) & 1) << 4);

    for (int t = 0; t < 16; t++) {
        if (t + 1 < 16) {
            load_tile(t + 1, cur ^ 1);
            asm volatile("cp.async.wait_group 1;" ::: "memory");
        } else {
            asm volatile("cp.async.wait_group 0;" ::: "memory");
        }
        __syncthreads();

        uint32_t sbufAh = sb + cur * BUF_U32 * 4;
        uint32_t sbufAl = sbufAh + MAT_U32 * 4;
        uint32_t sbufBh = sbufAl + MAT_U32 * 4;
        uint32_t sbufBl = sbufBh + MAT_U32 * 4;

#pragma unroll
        for (int ks = 0; ks < 2; ks++) {
            int ko = ks * 32;
            uint32_t aH[2][4], aL[2][4], bH[8][2], bL[8][2];
#pragma unroll
            for (int mt = 0; mt < 2; mt++) {
                uint32_t ra = aRowOff + mt * 16 * 80 + ko;
                LDM4(aH[mt][0], aH[mt][1], aH[mt][2], aH[mt][3], sbufAh + ra);
                LDM4(aL[mt][0], aL[mt][1], aL[mt][2], aL[mt][3], sbufAl + ra);
            }
#pragma unroll
            for (int p = 0; p < 4; p++) {
                uint32_t rb = bRowOff + p * 16 * 80 + ko;
                LDM4(bH[2 * p][0], bH[2 * p][1], bH[2 * p + 1][0], bH[2 * p + 1][1],
                     sbufBh + rb);
                LDM4(bL[2 * p][0], bL[2 * p][1], bL[2 * p + 1][0], bL[2 * p + 1][1],
                     sbufBl + rb);
            }
#pragma unroll
            for (int mt = 0; mt < 2; mt++)
#pragma unroll
                for (int nt = 0; nt < 8; nt++) {
                    mma16816(acc[mt][nt], aH[mt], bH[nt]);
                    mma16816(acc[mt][nt], aH[mt], bL[nt]);
                    mma16816(acc[mt][nt], aL[mt], bH[nt]);
                }
        }
        __syncthreads();
        cur ^= 1;
    }

    // epilogue
    const float* bias = mode ? g_bias2 : bias0;
#pragma unroll
    for (int mt = 0; mt < 2; mt++) {
#pragma unroll
        for (int nt = 0; nt < 8; nt++) {
            int r = mBase + warpM * 32 + mt * 16 + (lane >> 2);
            int c = nBase + warpN * 64 + nt * 8 + 2 * (lane & 3);
            float b0 = bias[c], b1v = bias[c + 1];
            float v0 = acc[mt][nt][0] + b0;
            float v1 = acc[mt][nt][1] + b1v;
            float v2 = acc[mt][nt][2] + b0;
            float v3 = acc[mt][nt][3] + b1v;
            if (mode == 0) {
                v0 = fmaxf(v0, 0.0f); v1 = fmaxf(v1, 0.0f);
                v2 = fmaxf(v2, 0.0f); v3 = fmaxf(v3, 0.0f);
            }
            if (mode == 0) {
                if (r < NN)     *(float2*)(g_h + (size_t)r * 512 + c)       = make_float2(v0, v1);
                if (r + 8 < NN) *(float2*)(g_h + (size_t)(r + 8) * 512 + c) = make_float2(v2, v3);
            } else {
                size_t half = (c < 256) ? 0 : (size_t)NN * 256;
                int cc = (c < 256) ? c : c - 256;
                if (r < NN)     *(float2*)(outp + half + (size_t)r * 256 + cc)       = make_float2(v0, v1);
                if (r + 8 < NN) *(float2*)(outp + half + (size_t)(r + 8) * 256 + cc) = make_float2(v2, v3);
            }
        }
    }
}

// ------------------------------- launch ------------------------------------
extern "C" void kernel_launch(void* const* d_in, const int* in_sizes, int n_in,
                              void* d_out, int out_size) {
    const float* x   = (const float*)d_in[0];
    const int*   ei  = (const int*)d_in[1];
    const float* W1  = (const float*)d_in[2];
    const float* b1  = (const float*)d_in[3];
    const float* Wmu = (const float*)d_in[4];
    const float* bmu = (const float*)d_in[5];
    const float* Wls = (const float*)d_in[6];
    const float* bls = (const float*)d_in[7];
    float* out = (float*)d_out;

    int N = in_sizes[0] / DH;
    int E = in_sizes[1] / 2;
    const int* srcp = ei;
    const int* dstp = ei + E;
    long long T = (long long)N * DH;

    static bool s_init = false;
    if (!s_init) {
        cudaFuncSetAttribute(k_tgemm, cudaFuncAttributeMaxDynamicSharedMemorySize,
                             SMEM_GEMM);
        s_init = true;
    }

    int nbE = (E + 255) / 256;              // 3125
    int nbW = 1024;                         // 512*512/256
    int nbX = (int)((T + 255) / 256);       // 100000

    k_deg_init<<<(N + 255) / 256, 256>>>(N);
    k_prep<<<nbE + 2 * nbW + nbX, 256>>>(x, dstp, W1, Wmu, Wls, bmu, bls,
                                         E, T, nbE, nbW);
    k_scan<<<1, 1024>>>(N);
    k_scatter<<<(E + 255) / 256, 256>>>(srcp, dstp, E);

    dim3 gmm(4, (N + 127) / 128);

    // layer 1
    k_agg<<<N, 128>>>(0);
    k_tgemm<<<gmm, 256, SMEM_GEMM>>>(b1, nullptr, 0);

    // layer 2 (fused mu | logstd)
    k_agg<<<N, 128>>>(1);
    k_tgemm<<<gmm, 256, SMEM_GEMM>>>(b1, out, 1);
}

// round 9
// speedup vs baseline: 3.4963x; 1.0041x over previous
#include <cuda_runtime.h>
#include <cuda_bf16.h>
#include <cstdint>

// ---------------------------------------------------------------------------
// VGAE/GCN encoder, round 8: bf16-split mma.sync GEMM w/ ldmatrix, coalesced
// tiled scan (+fused dinv), fused prep kernel (deg_accum|dropout|wprep).
// ---------------------------------------------------------------------------

#define NN 50000
#define EE 800000
#define DH 512

__device__ __align__(16) float g_Xd[(size_t)NN * DH];
__device__ __align__(16) float g_h [(size_t)NN * DH];
__device__ __align__(16) __nv_bfloat16 g_Zh[(size_t)NN * DH];
__device__ __align__(16) __nv_bfloat16 g_Zl[(size_t)NN * DH];
__device__ __align__(16) __nv_bfloat16 g_W1h[512 * 512];   // [N][K]
__device__ __align__(16) __nv_bfloat16 g_W1l[512 * 512];
__device__ __align__(16) __nv_bfloat16 g_W2h[512 * 512];   // fused [Wmu|Wls]
__device__ __align__(16) __nv_bfloat16 g_W2l[512 * 512];
__device__ float g_bias2[512];
__device__ float g_dinv[NN];
__device__ int   g_deg[NN];
__device__ int   g_rowptr[NN + 1];
__device__ int   g_cursor[NN];
__device__ int   g_csrc[EE];
__device__ float g_cw[EE];

// ----------------------------- threefry2x32 --------------------------------
__device__ __forceinline__ uint32_t rotl32(uint32_t v, int r) {
    return (v << r) | (v >> (32 - r));
}

__device__ __forceinline__ void threefry2x32(uint32_t k0, uint32_t k1,
                                             uint32_t& x0, uint32_t& x1) {
    uint32_t ks2 = 0x1BD11BDAu ^ k0 ^ k1;
    x0 += k0; x1 += k1;
#define TFR(r) { x0 += x1; x1 = rotl32(x1, r); x1 ^= x0; }
    TFR(13) TFR(15) TFR(26) TFR(6)
    x0 += k1;  x1 += ks2 + 1u;
    TFR(17) TFR(29) TFR(16) TFR(24)
    x0 += ks2; x1 += k0 + 2u;
    TFR(13) TFR(15) TFR(26) TFR(6)
    x0 += k0;  x1 += k1 + 3u;
    TFR(17) TFR(29) TFR(16) TFR(24)
    x0 += k1;  x1 += ks2 + 4u;
    TFR(13) TFR(15) TFR(26) TFR(6)
    x0 += ks2; x1 += k0 + 5u;
#undef TFR
}

__device__ __forceinline__ void bf16split(float w, __nv_bfloat16& h, __nv_bfloat16& l) {
    h = __float2bfloat16_rn(w);
    l = __float2bfloat16_rn(w - __bfloat162float(h));
}

// ----------------------------- graph prep ----------------------------------
__global__ void k_deg_init(int n) {
    int i = blockIdx.x * blockDim.x + threadIdx.x;
    if (i < n) g_deg[i] = 0;
}

// Fused independent prep: [deg_accum | wprep1 | wprep2 | dropout], by block.
__global__ void k_prep(const float* __restrict__ x, const int* __restrict__ dst,
                       const float* __restrict__ W1,
                       const float* __restrict__ Wmu, const float* __restrict__ Wls,
                       const float* __restrict__ bmu, const float* __restrict__ bls,
                       int E, long long T, int nbE, int nbW) {
    int b = blockIdx.x;
    int tid = threadIdx.x;
    if (b < nbE) {                                   // degree atomics
        int e = b * 256 + tid;
        if (e < E) atomicAdd(&g_deg[dst[e]], 1);
        return;
    }
    b -= nbE;
    if (b < nbW) {                                   // wprep1
        int idx = b * 256 + tid;
        int n = idx >> 9, k = idx & 511;
        bf16split(W1[k * 512 + n], g_W1h[idx], g_W1l[idx]);
        return;
    }
    b -= nbW;
    if (b < nbW) {                                   // wprep2 (+bias concat)
        int idx = b * 256 + tid;
        int n = idx >> 9, k = idx & 511;
        float w = (n < 256) ? Wmu[k * 256 + n] : Wls[k * 256 + (n - 256)];
        bf16split(w, g_W2h[idx], g_W2l[idx]);
        if (idx < 512) g_bias2[idx] = (idx < 256) ? bmu[idx] : bls[idx - 256];
        return;
    }
    b -= nbW;
    long long i = (long long)b * 256 + tid;          // dropout
    if (i >= T) return;
    uint32_t hi = 0u;
    uint32_t lo = (uint32_t)i;
    threefry2x32(0u, 42u, hi, lo);
    uint32_t bits = hi ^ lo;
    float u = __uint_as_float((bits >> 9) | 0x3f800000u) - 1.0f;
    g_Xd[i] = (u < 0.5f) ? x[i] * 2.0f : 0.0f;
}

// Tiled coalesced scan with carry; also writes g_dinv (fuses deg_finish).
__global__ void k_scan(int n) {
    __shared__ int wsum[32];
    __shared__ int s_carry;
    int tid = threadIdx.x, lane = tid & 31, w = tid >> 5;
    if (tid == 0) s_carry = 0;
    __syncthreads();
    for (int base = 0; base < n; base += 1024) {
        int i = base + tid;
        int v = (i < n) ? g_deg[i] : 0;
        if (i < n) g_dinv[i] = rsqrtf((float)v + 1.0f);
        int x = v;
#pragma unroll
        for (int o = 1; o < 32; o <<= 1) {
            int t = __shfl_up_sync(0xffffffffu, x, o);
            if (lane >= o) x += t;
        }
        if (lane == 31) wsum[w] = x;
        __syncthreads();
        if (w == 0) {
            int y = wsum[lane];
            int z = y;
#pragma unroll
            for (int o = 1; o < 32; o <<= 1) {
                int t = __shfl_up_sync(0xffffffffu, z, o);
                if (lane >= o) z += t;
            }
            wsum[lane] = z;                          // inclusive warp prefix
        }
        __syncthreads();
        int warpoff = (w == 0) ? 0 : wsum[w - 1];
        int c = s_carry;
        int excl = c + warpoff + x - v;
        if (i < n) {
            g_rowptr[i] = excl;
            g_cursor[i] = excl;
        }
        int total = wsum[31];
        __syncthreads();
        if (tid == 0) s_carry = c + total;
        __syncthreads();
    }
    if (tid == 0) g_rowptr[n] = s_carry;
}

__global__ void k_scatter(const int* __restrict__ src,
                          const int* __restrict__ dst, int E) {
    int e = blockIdx.x * blockDim.x + threadIdx.x;
    if (e >= E) return;
    int s = src[e];
    int d = dst[e];
    int pos = atomicAdd(&g_cursor[d], 1);
    g_csrc[pos] = s;
    g_cw[pos] = g_dinv[s] * g_dinv[d];
}

// ------------------------- CSR aggregation ---------------------------------
__global__ __launch_bounds__(128)
void k_agg(int which) {
    int node = blockIdx.x;
    int tid  = threadIdx.x;
    const float4* X4 = (const float4*)(which ? g_h : g_Xd);
    float dv = g_dinv[node];
    float w0 = dv * dv;
    float4 a = X4[(size_t)node * 128 + tid];
    float4 acc = make_float4(a.x * w0, a.y * w0, a.z * w0, a.w * w0);
    int e0 = g_rowptr[node];
    int e1 = g_rowptr[node + 1];
    for (int e = e0; e < e1; e++) {
        int   s = g_csrc[e];
        float w = g_cw[e];
        float4 v = X4[(size_t)s * 128 + tid];
        acc.x += v.x * w;
        acc.y += v.y * w;
        acc.z += v.z * w;
        acc.w += v.w * w;
    }
    __nv_bfloat16 hx, lx, hy, ly, hz, lz, hw, lw;
    bf16split(acc.x, hx, lx);
    bf16split(acc.y, hy, ly);
    bf16split(acc.z, hz, lz);
    bf16split(acc.w, hw, lw);
    __nv_bfloat162* Zh2 = (__nv_bfloat162*)g_Zh;
    __nv_bfloat162* Zl2 = (__nv_bfloat162*)g_Zl;
    size_t o = (size_t)node * 256 + tid * 2;
    Zh2[o]     = __nv_bfloat162(hx, hy);
    Zh2[o + 1] = __nv_bfloat162(hz, hw);
    Zl2[o]     = __nv_bfloat162(lx, ly);
    Zl2[o + 1] = __nv_bfloat162(lz, lw);
}

// --------------------------- tensor GEMM -----------------------------------
#define RSTRIDE 20                       // u32 per 32-bf16 row (80 bytes)
#define MAT_U32 (128 * RSTRIDE)
#define BUF_U32 (4 * MAT_U32)
#define SMEM_GEMM (2 * BUF_U32 * 4)

__device__ __forceinline__ void mma16816(float* c, const uint32_t* a, const uint32_t* b) {
    asm volatile(
        "mma.sync.aligned.m16n8k16.row.col.f32.bf16.bf16.f32 "
        "{%0,%1,%2,%3}, {%4,%5,%6,%7}, {%8,%9}, {%0,%1,%2,%3};"
        : "+f"(c[0]), "+f"(c[1]), "+f"(c[2]), "+f"(c[3])
        : "r"(a[0]), "r"(a[1]), "r"(a[2]), "r"(a[3]), "r"(b[0]), "r"(b[1]));
}

__device__ __forceinline__ void cpa16(uint32_t dst, const void* src) {
    asm volatile("cp.async.cg.shared.global [%0], [%1], 16;"
                 :: "r"(dst), "l"(src) : "memory");
}

#define LDM4(r0, r1, r2, r3, a) \
    asm volatile("ldmatrix.sync.aligned.m8n8.x4.shared.b16 {%0,%1,%2,%3}, [%4];" \
                 : "=r"(r0), "=r"(r1), "=r"(r2), "=r"(r3) : "r"(a))

__global__ __launch_bounds__(256, 1)
void k_tgemm(const float* __restrict__ bias0, float* __restrict__ outp, int mode) {
    extern __shared__ __align__(16) uint32_t smem[];
    uint32_t sb;
    asm("{ .reg .u64 t; cvta.to.shared.u64 t, %1; cvt.u32.u64 %0, t; }"
        : "=r"(sb) : "l"(smem));

    int tid = threadIdx.x, lane = tid & 31;
    int warpId = tid >> 5;
    int warpM = warpId & 3, warpN = warpId >> 2;
    int mBase = blockIdx.y * 128;
    int nBase = blockIdx.x * 128;

    const __nv_bfloat16* Ah = g_Zh;
    const __nv_bfloat16* Al = g_Zl;
    const __nv_bfloat16* Bh = mode ? g_W2h : g_W1h;
    const __nv_bfloat16* Bl = mode ? g_W2l : g_W1l;

    float acc[2][8][4];
#pragma unroll
    for (int i = 0; i < 2; i++)
#pragma unroll
        for (int j = 0; j < 8; j++)
#pragma unroll
            for (int c = 0; c < 4; c++) acc[i][j][c] = 0.0f;

    int ck0 = tid * 2, ck1 = tid * 2 + 1;
    int r0 = ck0 >> 2, q0 = (ck0 & 3);
    int r1 = ck1 >> 2, q1 = (ck1 & 3);
    int ar0 = min(mBase + r0, NN - 1);
    int ar1 = min(mBase + r1, NN - 1);
    int br0 = nBase + r0, br1 = nBase + r1;
    uint32_t d0 = sb + (r0 * RSTRIDE + q0 * 4) * 4;
    uint32_t d1 = sb + (r1 * RSTRIDE + q1 * 4) * 4;

    auto load_tile = [&](int t, int buf) {
        int k0 = t * 32;
        uint32_t bo = buf * BUF_U32 * 4;
        size_t a0o = (size_t)ar0 * 512 + k0 + q0 * 8;
        size_t a1o = (size_t)ar1 * 512 + k0 + q1 * 8;
        size_t b0o = (size_t)br0 * 512 + k0 + q0 * 8;
        size_t b1o = (size_t)br1 * 512 + k0 + q1 * 8;
        cpa16(d0 + bo,                Ah + a0o);
        cpa16(d1 + bo,                Ah + a1o);
        cpa16(d0 + bo + MAT_U32 * 4,  Al + a0o);
        cpa16(d1 + bo + MAT_U32 * 4,  Al + a1o);
        cpa16(d0 + bo + MAT_U32 * 8,  Bh + b0o);
        cpa16(d1 + bo + MAT_U32 * 8,  Bh + b1o);
        cpa16(d0 + bo + MAT_U32 * 12, Bl + b0o);
        cpa16(d1 + bo + MAT_U32 * 12, Bl + b1o);
        asm volatile("cp.async.commit_group;" ::: "memory");
    };

    load_tile(0, 0);
    int cur = 0;

    // ldmatrix lane address components (bytes within a matrix)
    int aRowOff = (warpM * 32 + (lane & 15)) * 80 + ((lane >> 4) << 4);
    int bRowOff = (warpN * 64 + ((lane >> 4) << 3) + (lane & 7)) * 80
                  + (((lane >> 3) & 1) << 4);

    for (int t = 0; t < 16; t++) {
        if (t + 1 < 16) {
            load_tile(t + 1, cur ^ 1);
            asm volatile("cp.async.wait_group 1;" ::: "memory");
        } else {
            asm volatile("cp.async.wait_group 0;" ::: "memory");
        }
        __syncthreads();

        uint32_t sbufAh = sb + cur * BUF_U32 * 4;
        uint32_t sbufAl = sbufAh + MAT_U32 * 4;
        uint32_t sbufBh = sbufAl + MAT_U32 * 4;
        uint32_t sbufBl = sbufBh + MAT_U32 * 4;

#pragma unroll
        for (int ks = 0; ks < 2; ks++) {
            int ko = ks * 32;
            uint32_t aH[2][4], aL[2][4], bH[8][2], bL[8][2];
#pragma unroll
            for (int mt = 0; mt < 2; mt++) {
                uint32_t ra = aRowOff + mt * 16 * 80 + ko;
                LDM4(aH[mt][0], aH[mt][1], aH[mt][2], aH[mt][3], sbufAh + ra);
                LDM4(aL[mt][0], aL[mt][1], aL[mt][2], aL[mt][3], sbufAl + ra);
            }
#pragma unroll
            for (int p = 0; p < 4; p++) {
                uint32_t rb = bRowOff + p * 16 * 80 + ko;
                LDM4(bH[2 * p][0], bH[2 * p][1], bH[2 * p + 1][0], bH[2 * p + 1][1],
                     sbufBh + rb);
                LDM4(bL[2 * p][0], bL[2 * p][1], bL[2 * p + 1][0], bL[2 * p + 1][1],
                     sbufBl + rb);
            }
#pragma unroll
            for (int mt = 0; mt < 2; mt++)
#pragma unroll
                for (int nt = 0; nt < 8; nt++) {
                    mma16816(acc[mt][nt], aH[mt], bH[nt]);
                    mma16816(acc[mt][nt], aH[mt], bL[nt]);
                    mma16816(acc[mt][nt], aL[mt], bH[nt]);
                }
        }
        __syncthreads();
        cur ^= 1;
    }

    // epilogue
    const float* bias = mode ? g_bias2 : bias0;
#pragma unroll
    for (int mt = 0; mt < 2; mt++) {
#pragma unroll
        for (int nt = 0; nt < 8; nt++) {
            int r = mBase + warpM * 32 + mt * 16 + (lane >> 2);
            int c = nBase + warpN * 64 + nt * 8 + 2 * (lane & 3);
            float b0 = bias[c], b1v = bias[c + 1];
            float v0 = acc[mt][nt][0] + b0;
            float v1 = acc[mt][nt][1] + b1v;
            float v2 = acc[mt][nt][2] + b0;
            float v3 = acc[mt][nt][3] + b1v;
            if (mode == 0) {
                v0 = fmaxf(v0, 0.0f); v1 = fmaxf(v1, 0.0f);
                v2 = fmaxf(v2, 0.0f); v3 = fmaxf(v3, 0.0f);
            }
            if (mode == 0) {
                if (r < NN)     *(float2*)(g_h + (size_t)r * 512 + c)       = make_float2(v0, v1);
                if (r + 8 < NN) *(float2*)(g_h + (size_t)(r + 8) * 512 + c) = make_float2(v2, v3);
            } else {
                size_t half = (c < 256) ? 0 : (size_t)NN * 256;
                int cc = (c < 256) ? c : c - 256;
                if (r < NN)     *(float2*)(outp + half + (size_t)r * 256 + cc)       = make_float2(v0, v1);
                if (r + 8 < NN) *(float2*)(outp + half + (size_t)(r + 8) * 256 + cc) = make_float2(v2, v3);
            }
        }
    }
}

// ------------------------------- launch ------------------------------------
extern "C" void kernel_launch(void* const* d_in, const int* in_sizes, int n_in,
                              void* d_out, int out_size) {
    const float* x   = (const float*)d_in[0];
    const int*   ei  = (const int*)d_in[1];
    const float* W1  = (const float*)d_in[2];
    const float* b1  = (const float*)d_in[3];
    const float* Wmu = (const float*)d_in[4];
    const float* bmu = (const float*)d_in[5];
    const float* Wls = (const float*)d_in[6];
    const float* bls = (const float*)d_in[7];
    float* out = (float*)d_out;

    int N = in_sizes[0] / DH;
    int E = in_sizes[1] / 2;
    const int* srcp = ei;
    const int* dstp = ei + E;
    long long T = (long long)N * DH;

    static bool s_init = false;
    if (!s_init) {
        cudaFuncSetAttribute(k_tgemm, cudaFuncAttributeMaxDynamicSharedMemorySize,
                             SMEM_GEMM);
        s_init = true;
    }

    int nbE = (E + 255) / 256;              // 3125
    int nbW = 1024;                         // 512*512/256
    int nbX = (int)((T + 255) / 256);       // 100000

    k_deg_init<<<(N + 255) / 256, 256>>>(N);
    k_prep<<<nbE + 2 * nbW + nbX, 256>>>(x, dstp, W1, Wmu, Wls, bmu, bls,
                                         E, T, nbE, nbW);
    k_scan<<<1, 1024>>>(N);
    k_scatter<<<(E + 255) / 256, 256>>>(srcp, dstp, E);

    dim3 gmm(4, (N + 127) / 128);

    // layer 1
    k_agg<<<N, 128>>>(0);
    k_tgemm<<<gmm, 256, SMEM_GEMM>>>(b1, nullptr, 0);

    // layer 2 (fused mu | logstd)
    k_agg<<<N, 128>>>(1);
    k_tgemm<<<gmm, 256, SMEM_GEMM>>>(b1, out, 1);
}